// round 16
// baseline (speedup 1.0000x reference)
#include <cuda_runtime.h>
#include <math.h>

#define NPIX0 (512*512)

// Scratch (allocation-free: __device__ globals)
__device__ unsigned char  g_labels[NPIX0];       // 256 KB
__device__ unsigned short g_mask1[256*256];      // 128 KB
__device__ unsigned short g_mask2[128*128];      // 32 KB
__device__ unsigned short g_mask3[64*64];        // 8 KB
__device__ int            g_parts[16*480];       // vec as int-bits of non-neg floats

// ---------------------------------------------------------------------------
// Kernel A: argmax over 16 channels + fused copy of encoded to output +
// pooled label bitmasks (tile-local 2x2 OR pooling) + zero parts.
// Block (32,8); each thread owns 2 consecutive pixels (float2).
// Tile: 64 wide x 8 tall. Grid (8, 64) = 512 blocks.
// ---------------------------------------------------------------------------
__global__ void kA(const float* __restrict__ enc, float* __restrict__ out_enc) {
    int tx = threadIdx.x, ty = threadIdx.y;
    int x2 = (blockIdx.x * 32 + tx) * 2;
    int y  = blockIdx.y * 8 + ty;
    int px = y * 512 + x2;
    int p2 = px >> 1;

    const float2* e2 = (const float2*)enc;
    float2*       o2 = (float2*)out_enc;

    float2 v = e2[p2];
    if (o2) o2[p2] = v;
    float b0 = v.x, b1v = v.y;
    int i0 = 0, i1 = 0;
#pragma unroll
    for (int c = 1; c < 16; c++) {
        float2 w = e2[c * (NPIX0 / 2) + p2];
        if (o2) o2[c * (NPIX0 / 2) + p2] = w;
        if (w.x > b0)  { b0 = w.x;  i0 = c; }
        if (w.y > b1v) { b1v = w.y; i1 = c; }
    }
    *(uchar2*)&g_labels[px] = make_uchar2((unsigned char)i0, (unsigned char)i1);

    // Level-1 cells (2x2 px): tile has 4 rows x 32 cols.
    __shared__ unsigned int sh1[128];
    __shared__ unsigned int sh2[32];   // level-2: 2 rows x 16 cols
    __shared__ unsigned int sh3[8];    // level-3: 1 row  x 8 cols
    int tid = ty * 32 + tx;
    if (tid < 128) sh1[tid] = 0;
    if (tid < 32)  sh2[tid] = 0;
    if (tid < 8)   sh3[tid] = 0;
    __syncthreads();

    atomicOr(&sh1[(ty >> 1) * 32 + tx], (1u << i0) | (1u << i1));
    __syncthreads();

    if (tid < 128) {
        int r1 = tid >> 5, c1 = tid & 31;
        unsigned m = sh1[tid];
        g_mask1[(blockIdx.y * 4 + r1) * 256 + blockIdx.x * 32 + c1] =
            (unsigned short)m;
        atomicOr(&sh2[(r1 >> 1) * 16 + (c1 >> 1)], m);
    }
    __syncthreads();
    if (tid < 32) {
        int r2 = tid >> 4, c2 = tid & 15;
        unsigned m = sh2[tid];
        g_mask2[(blockIdx.y * 2 + r2) * 128 + blockIdx.x * 16 + c2] =
            (unsigned short)m;
        atomicOr(&sh3[c2 >> 1], m);
    }
    __syncthreads();
    if (tid < 8)
        g_mask3[blockIdx.y * 64 + blockIdx.x * 8 + tid] = (unsigned short)sh3[tid];

    if (blockIdx.x == 0 && blockIdx.y == 0)
        for (int i = tid; i < 16 * 480; i += 256) g_parts[i] = 0;
}

// Shared slow-path/fast-path element processor.
// smax entries are int bit patterns of non-negative floats (order-preserving).
#define PROC(V, I)                                                             \
    {                                                                          \
        float _vm = fmaxf(fmaxf((V).x, (V).y), fmaxf((V).z, (V).w));           \
        if (_vm > thr) {                                                       \
            float _arr[4] = {(V).x, (V).y, (V).z, (V).w};                      \
            int _px0 = base + (I) * 4;                                         \
            _Pragma("unroll")                                                  \
            for (int _j = 0; _j < 4; _j++) {                                   \
                float _vj = _arr[_j];                                          \
                if (_vj <= thr) continue;                                      \
                int _px = _px0 + _j;                                           \
                unsigned _m;                                                   \
                if (level == 0)      _m = 1u << g_labels[_px];                 \
                else if (level == 1) _m = g_mask1[_px];                        \
                else if (level == 2) _m = g_mask2[_px];                        \
                else                 _m = g_mask3[_px];                        \
                int _vb = __float_as_int(_vj);                                 \
                while (_m) {                                                   \
                    int _k = __ffs(_m) - 1;                                    \
                    _m &= _m - 1;                                              \
                    if (_vb > vs[_k]) atomicMax((int*)&smax[_k], _vb);         \
                }                                                              \
            }                                                                  \
            int _mn = vs[0];                                                   \
            _Pragma("unroll")                                                  \
            for (int _k = 1; _k < 16; _k++) _mn = min(_mn, vs[_k]);            \
            thr = __int_as_float(_mn);                                         \
        }                                                                      \
    }

// ---------------------------------------------------------------------------
// Kernel B (sampler): one block per channel (480 blocks x 256 thr). Slow path
// over a contiguous 2048-element sample; publishes per-(label,channel) maxima
// into g_parts so kC blocks start with converged thresholds.
// ---------------------------------------------------------------------------
__global__ void __launch_bounds__(256) kB(const float* __restrict__ f0,
                                          const float* __restrict__ f1,
                                          const float* __restrict__ f2,
                                          const float* __restrict__ f3) {
    __shared__ int smax[16];
    int tid = threadIdx.x;
    if (tid < 16) smax[tid] = 0;
    __syncthreads();

    int b = blockIdx.x;
    const float* f;
    int level, col = b;
    if (b < 32)        { level = 0; f = f0 + b * NPIX0; }
    else if (b < 96)   { level = 1; f = f1 + (b - 32) * 65536; }
    else if (b < 224)  { level = 2; f = f2 + (b - 96) * 16384; }
    else               { level = 3; f = f3 + (b - 224) * 4096; }
    int base = 0;   // sample = first 2048 elements of the channel

    volatile int* vs = smax;
    float thr = 0.0f;
    const float4* fv = (const float4*)f;

    float4 v0 = fv[tid];
    float4 v1 = fv[tid + 256];
    PROC(v0, tid)
    PROC(v1, tid + 256)

    __syncthreads();
    if (tid < 16) atomicMax(&g_parts[tid * 480 + col], smax[tid]);
}

// ---------------------------------------------------------------------------
// Kernel C: masked per-label max, 16K-element chunks (1152 blocks), seeded
// from g_parts (monotone lower bounds). 8-deep upfront-loaded batches for
// the 4096-float4 chunks (2 iterations); f3 chunks (1024 f4) use one 4-deep
// batch. More outstanding loads per thread = better latency hiding.
// ---------------------------------------------------------------------------
__global__ void __launch_bounds__(256) kC(const float* __restrict__ f0,
                                          const float* __restrict__ f1,
                                          const float* __restrict__ f2,
                                          const float* __restrict__ f3) {
    __shared__ int smax[16];
    int tid = threadIdx.x;

    int b = blockIdx.x;
    const float* f;
    int level, base, col, n4;
    if (b < 512) {             // f0: 32 ch x 16 chunks of 16384
        int ch = b >> 4; level = 0; base = (b & 15) * 16384;
        f = f0 + ch * NPIX0; col = ch; n4 = 4096;
    } else if (b < 768) {      // f1: 64 ch x 4 chunks of 16384
        int i = b - 512; int ch = i >> 2; level = 1; base = (i & 3) * 16384;
        f = f1 + ch * 65536; col = 32 + ch; n4 = 4096;
    } else if (b < 896) {      // f2: 128 ch x 1 chunk of 16384
        int ch = b - 768; level = 2; base = 0;
        f = f2 + ch * 16384; col = 96 + ch; n4 = 4096;
    } else {                   // f3: 256 ch x 1 chunk of 4096
        int ch = b - 896; level = 3; base = 0;
        f = f3 + ch * 4096; col = 224 + ch; n4 = 1024;
    }

    // Seed thresholds from sampler output (valid lower bounds: monotone).
    if (tid < 16) smax[tid] = g_parts[tid * 480 + col];
    __syncthreads();

    volatile int* vs = smax;
    float thr;
    {
        int mn = vs[0];
#pragma unroll
        for (int k = 1; k < 16; k++) mn = min(mn, vs[k]);
        thr = __int_as_float(mn);
    }
    const float4* fv = (const float4*)(f + base);

    if (n4 == 4096) {
        for (int off = 0; off < 4096; off += 2048) {
            float4 v0 = fv[off + tid];
            float4 v1 = fv[off + tid + 256];
            float4 v2 = fv[off + tid + 512];
            float4 v3 = fv[off + tid + 768];
            float4 v4 = fv[off + tid + 1024];
            float4 v5 = fv[off + tid + 1280];
            float4 v6 = fv[off + tid + 1536];
            float4 v7 = fv[off + tid + 1792];
            PROC(v0, off + tid)
            PROC(v1, off + tid + 256)
            PROC(v2, off + tid + 512)
            PROC(v3, off + tid + 768)
            PROC(v4, off + tid + 1024)
            PROC(v5, off + tid + 1280)
            PROC(v6, off + tid + 1536)
            PROC(v7, off + tid + 1792)
        }
    } else {
        float4 v0 = fv[tid];
        float4 v1 = fv[tid + 256];
        float4 v2 = fv[tid + 512];
        float4 v3 = fv[tid + 768];
        PROC(v0, tid)
        PROC(v1, tid + 256)
        PROC(v2, tid + 512)
        PROC(v3, tid + 768)
    }

    __syncthreads();
    if (tid < 16) atomicMax(&g_parts[tid * 480 + col], smax[tid]);
}

// ---------------------------------------------------------------------------
// Kernel M: fused MLP. 16 blocks (one per label row) x 512 thr.
// Layer1 v2: thread = (4-column group, K-slice): 60 LDG.128 of W1 feeding
// 4 independent FMA chains (was 240 scalar strided loads, 1 chain).
// 8-way K-split reduced in shared. Layer2: 4 warp reductions + sigmoid.
// ---------------------------------------------------------------------------
__global__ void __launch_bounds__(512) kM(const float* __restrict__ W1,
                                          const float* __restrict__ b1,
                                          const float* __restrict__ W2,
                                          const float* __restrict__ b2,
                                          float* __restrict__ out_bbox) {
    __shared__ float  sv[480];
    __shared__ float4 sp4[480];    // partials: [slice 0..7][colgroup 0..59]
    __shared__ float  sh[240];     // hidden
    int t = threadIdx.x;
    int r = blockIdx.x;

    if (t < 480) sv[t] = __int_as_float(((const int*)g_parts)[r * 480 + t]);
    __syncthreads();

    if (t < 480) {
        int cg = t % 60, slice = t / 60;       // 60 col-groups x 8 K-slices
        const float4* w4 = (const float4*)(W1 + slice * 60 * 240) + cg;
        const float*  vp = sv + slice * 60;
        float4 acc = make_float4(0.f, 0.f, 0.f, 0.f);
#pragma unroll 15
        for (int i = 0; i < 60; i++) {
            float4 w = w4[i * 60];             // W1[slice*60+i][4cg..4cg+3]
            float  x = vp[i];
            acc.x += x * w.x;
            acc.y += x * w.y;
            acc.z += x * w.z;
            acc.w += x * w.w;
        }
        sp4[slice * 60 + cg] = acc;
    }
    __syncthreads();

    if (t < 240) {
        int cg = t >> 2, comp = t & 3;
        float a = 0.0f;
#pragma unroll
        for (int s = 0; s < 8; s++)
            a += ((const float*)&sp4[s * 60 + cg])[comp];
        sh[t] = a + b1[t];
    }
    __syncthreads();

    if (t < 128) {
        int j = t >> 5, lane = t & 31;
        float acc = 0.0f;
        for (int k = lane; k < 240; k += 32)
            acc += sh[k] * W2[k * 4 + j];
#pragma unroll
        for (int o = 16; o > 0; o >>= 1)
            acc += __shfl_down_sync(0xFFFFFFFFu, acc, o);
        if (lane == 0 && r >= 1 && out_bbox)
            out_bbox[(r - 1) * 4 + j] = 1.0f / (1.0f + expf(-(acc + b2[j])));
    }
}

extern "C" void kernel_launch(void* const* d_in, const int* in_sizes, int n_in,
                              void* d_out, int out_size) {
    const float* enc = (const float*)d_in[0];
    const float* f0  = (const float*)d_in[1];
    const float* f1  = (const float*)d_in[2];
    const float* f2  = (const float*)d_in[3];
    const float* f3  = (const float*)d_in[4];
    const float* W1  = (const float*)d_in[5];
    const float* b1  = (const float*)d_in[6];
    const float* W2  = (const float*)d_in[7];
    const float* b2  = (const float*)d_in[8];
    float* out = (float*)d_out;

    // Output layout: (bbox[1,15,4], encoded[1,16,512,512]) flattened in order.
    float* out_bbox = nullptr;
    float* out_enc  = nullptr;
    const int ENC_N = 16 * NPIX0;
    if (out_size >= 60 + ENC_N) { out_bbox = out; out_enc = out + 60; }
    else if (out_size >= ENC_N) { out_enc = out; }
    else                        { out_bbox = out; }

    dim3 blkA(32, 8), grdA(8, 64);
    kA<<<grdA, blkA>>>(enc, out_enc);
    kB<<<480, 256>>>(f0, f1, f2, f3);
    kC<<<1152, 256>>>(f0, f1, f2, f3);
    kM<<<16, 512>>>(W1, b1, W2, b2, out_bbox);
}

// round 17
// speedup vs baseline: 1.1983x; 1.1983x over previous
#include <cuda_runtime.h>
#include <math.h>

#define NPIX0 (512*512)

// Scratch (allocation-free: __device__ globals)
__device__ unsigned char  g_labels[NPIX0];       // 256 KB
__device__ unsigned short g_mask1[256*256];      // 128 KB
__device__ unsigned short g_mask2[128*128];      // 32 KB
__device__ unsigned short g_mask3[64*64];        // 8 KB
__device__ int            g_parts[16*480];       // vec as int-bits of non-neg floats

// ---------------------------------------------------------------------------
// Kernel A: argmax over 16 channels + fused copy of encoded to output +
// pooled label bitmasks (tile-local 2x2 OR pooling) + zero parts.
// Block (32,8); each thread owns 2 consecutive pixels (float2).
// Tile: 64 wide x 8 tall. Grid (8, 64) = 512 blocks.
// ---------------------------------------------------------------------------
__global__ void kA(const float* __restrict__ enc, float* __restrict__ out_enc) {
    int tx = threadIdx.x, ty = threadIdx.y;
    int x2 = (blockIdx.x * 32 + tx) * 2;
    int y  = blockIdx.y * 8 + ty;
    int px = y * 512 + x2;
    int p2 = px >> 1;

    const float2* e2 = (const float2*)enc;
    float2*       o2 = (float2*)out_enc;

    float2 v = e2[p2];
    if (o2) o2[p2] = v;
    float b0 = v.x, b1v = v.y;
    int i0 = 0, i1 = 0;
#pragma unroll
    for (int c = 1; c < 16; c++) {
        float2 w = e2[c * (NPIX0 / 2) + p2];
        if (o2) o2[c * (NPIX0 / 2) + p2] = w;
        if (w.x > b0)  { b0 = w.x;  i0 = c; }
        if (w.y > b1v) { b1v = w.y; i1 = c; }
    }
    *(uchar2*)&g_labels[px] = make_uchar2((unsigned char)i0, (unsigned char)i1);

    // Level-1 cells (2x2 px): tile has 4 rows x 32 cols.
    __shared__ unsigned int sh1[128];
    __shared__ unsigned int sh2[32];   // level-2: 2 rows x 16 cols
    __shared__ unsigned int sh3[8];    // level-3: 1 row  x 8 cols
    int tid = ty * 32 + tx;
    if (tid < 128) sh1[tid] = 0;
    if (tid < 32)  sh2[tid] = 0;
    if (tid < 8)   sh3[tid] = 0;
    __syncthreads();

    atomicOr(&sh1[(ty >> 1) * 32 + tx], (1u << i0) | (1u << i1));
    __syncthreads();

    if (tid < 128) {
        int r1 = tid >> 5, c1 = tid & 31;
        unsigned m = sh1[tid];
        g_mask1[(blockIdx.y * 4 + r1) * 256 + blockIdx.x * 32 + c1] =
            (unsigned short)m;
        atomicOr(&sh2[(r1 >> 1) * 16 + (c1 >> 1)], m);
    }
    __syncthreads();
    if (tid < 32) {
        int r2 = tid >> 4, c2 = tid & 15;
        unsigned m = sh2[tid];
        g_mask2[(blockIdx.y * 2 + r2) * 128 + blockIdx.x * 16 + c2] =
            (unsigned short)m;
        atomicOr(&sh3[c2 >> 1], m);
    }
    __syncthreads();
    if (tid < 8)
        g_mask3[blockIdx.y * 64 + blockIdx.x * 8 + tid] = (unsigned short)sh3[tid];

    if (blockIdx.x == 0 && blockIdx.y == 0)
        for (int i = tid; i < 16 * 480; i += 256) g_parts[i] = 0;
}

// Shared slow-path/fast-path element processor.
// smax entries are int bit patterns of non-negative floats (order-preserving).
#define PROC(V, I)                                                             \
    {                                                                          \
        float _vm = fmaxf(fmaxf((V).x, (V).y), fmaxf((V).z, (V).w));           \
        if (_vm > thr) {                                                       \
            float _arr[4] = {(V).x, (V).y, (V).z, (V).w};                      \
            int _px0 = base + (I) * 4;                                         \
            _Pragma("unroll")                                                  \
            for (int _j = 0; _j < 4; _j++) {                                   \
                float _vj = _arr[_j];                                          \
                if (_vj <= thr) continue;                                      \
                int _px = _px0 + _j;                                           \
                unsigned _m;                                                   \
                if (level == 0)      _m = 1u << g_labels[_px];                 \
                else if (level == 1) _m = g_mask1[_px];                        \
                else if (level == 2) _m = g_mask2[_px];                        \
                else                 _m = g_mask3[_px];                        \
                int _vb = __float_as_int(_vj);                                 \
                while (_m) {                                                   \
                    int _k = __ffs(_m) - 1;                                    \
                    _m &= _m - 1;                                              \
                    if (_vb > vs[_k]) atomicMax((int*)&smax[_k], _vb);         \
                }                                                              \
            }                                                                  \
            int _mn = vs[0];                                                   \
            _Pragma("unroll")                                                  \
            for (int _k = 1; _k < 16; _k++) _mn = min(_mn, vs[_k]);            \
            thr = __int_as_float(_mn);                                         \
        }                                                                      \
    }

// ---------------------------------------------------------------------------
// Kernel B (sampler): one block per channel (480 blocks x 256 thr). Slow path
// over a contiguous 2048-element sample; publishes per-(label,channel) maxima
// into g_parts so kC blocks start with converged thresholds.
// ---------------------------------------------------------------------------
__global__ void __launch_bounds__(256) kB(const float* __restrict__ f0,
                                          const float* __restrict__ f1,
                                          const float* __restrict__ f2,
                                          const float* __restrict__ f3) {
    __shared__ int smax[16];
    int tid = threadIdx.x;
    if (tid < 16) smax[tid] = 0;
    __syncthreads();

    int b = blockIdx.x;
    const float* f;
    int level, col = b;
    if (b < 32)        { level = 0; f = f0 + b * NPIX0; }
    else if (b < 96)   { level = 1; f = f1 + (b - 32) * 65536; }
    else if (b < 224)  { level = 2; f = f2 + (b - 96) * 16384; }
    else               { level = 3; f = f3 + (b - 224) * 4096; }
    int base = 0;   // sample = first 2048 elements of the channel

    volatile int* vs = smax;
    float thr = 0.0f;
    const float4* fv = (const float4*)f;

    float4 v0 = fv[tid];
    float4 v1 = fv[tid + 256];
    PROC(v0, tid)
    PROC(v1, tid + 256)

    __syncthreads();
    if (tid < 16) atomicMax(&g_parts[tid * 480 + col], smax[tid]);
}

// ---------------------------------------------------------------------------
// Kernel C: masked per-label max, 16K-element chunks (1152 blocks), seeded
// from g_parts (monotone: any read is a valid lower bound). Pure streaming:
// aligned 4-deep upfront-loaded batches (R15-measured-best structure).
// Block map: f0 512 (32ch x 16), f1 256 (64 x 4), f2 128 (128 x 1),
//            f3 256 (256 x 1, 4K elems).
// ---------------------------------------------------------------------------
__global__ void __launch_bounds__(256) kC(const float* __restrict__ f0,
                                          const float* __restrict__ f1,
                                          const float* __restrict__ f2,
                                          const float* __restrict__ f3) {
    __shared__ int smax[16];
    int tid = threadIdx.x;

    int b = blockIdx.x;
    const float* f;
    int level, base, col, n4;
    if (b < 512) {             // f0: 32 ch x 16 chunks of 16384
        int ch = b >> 4; level = 0; base = (b & 15) * 16384;
        f = f0 + ch * NPIX0; col = ch; n4 = 4096;
    } else if (b < 768) {      // f1: 64 ch x 4 chunks of 16384
        int i = b - 512; int ch = i >> 2; level = 1; base = (i & 3) * 16384;
        f = f1 + ch * 65536; col = 32 + ch; n4 = 4096;
    } else if (b < 896) {      // f2: 128 ch x 1 chunk of 16384
        int ch = b - 768; level = 2; base = 0;
        f = f2 + ch * 16384; col = 96 + ch; n4 = 4096;
    } else {                   // f3: 256 ch x 1 chunk of 4096
        int ch = b - 896; level = 3; base = 0;
        f = f3 + ch * 4096; col = 224 + ch; n4 = 1024;
    }

    // Seed thresholds from the sampler's output (valid lower bounds).
    if (tid < 16) smax[tid] = g_parts[tid * 480 + col];
    __syncthreads();

    volatile int* vs = smax;
    float thr;
    {
        int mn = vs[0];
#pragma unroll
        for (int k = 1; k < 16; k++) mn = min(mn, vs[k]);
        thr = __int_as_float(mn);
    }
    const float4* fv = (const float4*)(f + base);

    // Pure streaming: aligned batches of 4 float4/thread, loads upfront.
    for (int off = 0; off < n4; off += 1024) {
        float4 v0 = fv[off + tid];
        float4 v1 = fv[off + tid + 256];
        float4 v2 = fv[off + tid + 512];
        float4 v3 = fv[off + tid + 768];
        PROC(v0, off + tid)
        PROC(v1, off + tid + 256)
        PROC(v2, off + tid + 512)
        PROC(v3, off + tid + 768)
    }

    __syncthreads();
    if (tid < 16) atomicMax(&g_parts[tid * 480 + col], smax[tid]);
}

// ---------------------------------------------------------------------------
// Kernel M: fused MLP. 16 blocks (one per label row) x 1024 thr.
// Layer1 v3: thread = (4-col group cg 0..59, K-slice 0..15): 30 LDG.128 of
// W1 per thread, fully unrolled, __launch_bounds__(1024,1) for reg headroom
// -> deep load pipeline instead of the reg-starved 32-reg serialization
// that kept kM at 16us. Layer2: 4 warp reductions + sigmoid.
// ---------------------------------------------------------------------------
__global__ void __launch_bounds__(1024, 1) kM(const float* __restrict__ W1,
                                              const float* __restrict__ b1,
                                              const float* __restrict__ W2,
                                              const float* __restrict__ b2,
                                              float* __restrict__ out_bbox) {
    __shared__ float  sv[480];
    __shared__ float4 sp4[960];    // partials: [slice 0..15][colgroup 0..59]
    __shared__ float  sh[240];     // hidden
    int t = threadIdx.x;
    int r = blockIdx.x;

    if (t < 480) sv[t] = __int_as_float(((const int*)g_parts)[r * 480 + t]);
    __syncthreads();

    if (t < 960) {
        int cg = t % 60, slice = t / 60;       // 60 col-groups x 16 K-slices
        const float4* w4 = (const float4*)(W1 + slice * 30 * 240) + cg;
        const float*  vp = sv + slice * 30;
        float4 acc = make_float4(0.f, 0.f, 0.f, 0.f);
#pragma unroll
        for (int i = 0; i < 30; i++) {
            float4 w = w4[i * 60];             // W1[slice*30+i][4cg..4cg+3]
            float  x = vp[i];
            acc.x += x * w.x;
            acc.y += x * w.y;
            acc.z += x * w.z;
            acc.w += x * w.w;
        }
        sp4[t] = acc;                          // t == slice*60 + cg
    }
    __syncthreads();

    if (t < 240) {
        int cg = t >> 2, comp = t & 3;
        float a = 0.0f;
#pragma unroll
        for (int s = 0; s < 16; s++)
            a += ((const float*)&sp4[s * 60 + cg])[comp];
        sh[t] = a + b1[t];
    }
    __syncthreads();

    if (t < 128) {
        int j = t >> 5, lane = t & 31;
        float acc = 0.0f;
        for (int k = lane; k < 240; k += 32)
            acc += sh[k] * W2[k * 4 + j];
#pragma unroll
        for (int o = 16; o > 0; o >>= 1)
            acc += __shfl_down_sync(0xFFFFFFFFu, acc, o);
        if (lane == 0 && r >= 1 && out_bbox)
            out_bbox[(r - 1) * 4 + j] = 1.0f / (1.0f + expf(-(acc + b2[j])));
    }
}

extern "C" void kernel_launch(void* const* d_in, const int* in_sizes, int n_in,
                              void* d_out, int out_size) {
    const float* enc = (const float*)d_in[0];
    const float* f0  = (const float*)d_in[1];
    const float* f1  = (const float*)d_in[2];
    const float* f2  = (const float*)d_in[3];
    const float* f3  = (const float*)d_in[4];
    const float* W1  = (const float*)d_in[5];
    const float* b1  = (const float*)d_in[6];
    const float* W2  = (const float*)d_in[7];
    const float* b2  = (const float*)d_in[8];
    float* out = (float*)d_out;

    // Output layout: (bbox[1,15,4], encoded[1,16,512,512]) flattened in order.
    float* out_bbox = nullptr;
    float* out_enc  = nullptr;
    const int ENC_N = 16 * NPIX0;
    if (out_size >= 60 + ENC_N) { out_bbox = out; out_enc = out + 60; }
    else if (out_size >= ENC_N) { out_enc = out; }
    else                        { out_bbox = out; }

    dim3 blkA(32, 8), grdA(8, 64);
    kA<<<grdA, blkA>>>(enc, out_enc);
    kB<<<480, 256>>>(f0, f1, f2, f3);
    kC<<<1152, 256>>>(f0, f1, f2, f3);
    kM<<<16, 1024>>>(W1, b1, W2, b2, out_bbox);
}